// round 15
// baseline (speedup 1.0000x reference)
#include <cuda_runtime.h>
#include <cuda_fp16.h>
#include <mma.h>
#include <cstdint>

using namespace nvcuda;

#define NN 4096         // N_NODES
#define IF 256          // IN_FEAT
#define NH 8            // N_HEADS
#define HID 64          // N_HIDDEN
#define OF 512          // NH*HID
#define NEG_SLOPE 0.2f
#define MAX_DEG 512     // binomial(4096,0.05): mean 205, max ~265

// Scratch (device globals: no allocation allowed).
__device__ __align__(16) uint2 g_half[NN * 128];    // g in fp16, [4096][512] (4 MB)
__device__ __align__(16) float g_el[NN * NH];
__device__ __align__(16) float g_er[NN * NH];
__device__ __align__(16) float g_gsum_part[32 * OF];
__device__ __align__(16) float g_gsum[OF];
__device__ __align__(16) unsigned g_bitmask[NN * 128];  // adjacency bitmasks (2 MB)

// ---------------------------------------------------------------------------
// Bitmask kernel: warp per row, ballot scan of adj -> 128 u32 words per row.
// Runs on a forked stream, overlapped with the GEMM (independent inputs).
// ---------------------------------------------------------------------------
__global__ __launch_bounds__(256) void bitmask_kernel(const float* __restrict__ adj) {
    const int warp = threadIdx.x >> 5, lane = threadIdx.x & 31;
    const int i = blockIdx.x * 8 + warp;
    const float* arow = adj + (size_t)i * NN;
    unsigned* brow = g_bitmask + (size_t)i * 128;
#pragma unroll 4
    for (int k = 0; k < 128; k++) {
        float v = __ldg(&arow[k * 32 + lane]);
        unsigned m = __ballot_sync(0xFFFFFFFFu, v != 0.f);
        if (lane == 0) brow[k] = m;
    }
}

// ---------------------------------------------------------------------------
// WMMA GEMM: g[i,o] = sum_k h[i,k]*W[o,k].  M=4096, N=512, K=256.
// 128x128 tile, 256 thr (8 warps), grid 4x32 = 128 CTAs = ONE wave.
// In-kernel fp32->fp16 conversion while staging (whole K in smem, one sync).
// Warp (wr,wc): 32x64 warp tile -> cfrag[2][4].
// C -> smem (aliased over staging) -> warp-local epilogue.
// ---------------------------------------------------------------------------
#define HS_STRIDE 264                              // halves/row (256+8 pad), 16B-mult
#define WS_OFF (128 * HS_STRIDE)                   // in halves
#define GM_SMEM ((128 + 128) * HS_STRIDE * 2)      // 135168 B

__global__ __launch_bounds__(256) void gemm_wmma_kernel(const float* __restrict__ h,
                                                        const float* __restrict__ W,
                                                        const float* __restrict__ a) {
    extern __shared__ __align__(16) char dynsm[];
    __half* hs = (__half*)dynsm;                   // [128][264]
    __half* ws = (__half*)dynsm + WS_OFF;          // [128][264]
    float*  cs = (float*)dynsm;                    // [128][128], aliases hs after mainloop
    __shared__ float colsum[128];

    const int t = threadIdx.x, lane = t & 31, w = t >> 5;
    const int o0 = blockIdx.x * 128, i0 = blockIdx.y * 128;

    if (t < 128) colsum[t] = 0.f;

#pragma unroll
    for (int l = t; l < 128 * 64; l += 256) {
        int row = l >> 6, c4 = l & 63;
        float4 v = *(const float4*)&h[(size_t)(i0 + row) * IF + c4 * 4];
        __half2 p0 = __floats2half2_rn(v.x, v.y);
        __half2 p1 = __floats2half2_rn(v.z, v.w);
        *(uint2*)&hs[row * HS_STRIDE + c4 * 4] =
            make_uint2(*(const unsigned*)&p0, *(const unsigned*)&p1);
    }
#pragma unroll
    for (int l = t; l < 128 * 64; l += 256) {
        int row = l >> 6, c4 = l & 63;
        float4 v = *(const float4*)&W[(size_t)(o0 + row) * IF + c4 * 4];
        __half2 p0 = __floats2half2_rn(v.x, v.y);
        __half2 p1 = __floats2half2_rn(v.z, v.w);
        *(uint2*)&ws[row * HS_STRIDE + c4 * 4] =
            make_uint2(*(const unsigned*)&p0, *(const unsigned*)&p1);
    }
    __syncthreads();

    const int wr = w >> 1, wc = w & 1;
    wmma::fragment<wmma::accumulator, 16, 16, 16, float> cfrag[2][4];
#pragma unroll
    for (int m = 0; m < 2; m++)
#pragma unroll
        for (int f = 0; f < 4; f++) wmma::fill_fragment(cfrag[m][f], 0.f);

#pragma unroll
    for (int kf = 0; kf < 16; kf++) {
        wmma::fragment<wmma::matrix_a, 16, 16, 16, __half, wmma::row_major> afrag[2];
#pragma unroll
        for (int m = 0; m < 2; m++)
            wmma::load_matrix_sync(afrag[m],
                hs + (wr * 32 + m * 16) * HS_STRIDE + kf * 16, HS_STRIDE);
#pragma unroll
        for (int f = 0; f < 4; f++) {
            wmma::fragment<wmma::matrix_b, 16, 16, 16, __half, wmma::col_major> bfrag;
            wmma::load_matrix_sync(bfrag,
                ws + (wc * 64 + f * 16) * HS_STRIDE + kf * 16, HS_STRIDE);
#pragma unroll
            for (int m = 0; m < 2; m++)
                wmma::mma_sync(cfrag[m][f], afrag[m], bfrag, cfrag[m][f]);
        }
    }
    __syncthreads();   // all reads of hs/ws done before cs (aliased) is written
#pragma unroll
    for (int m = 0; m < 2; m++)
#pragma unroll
        for (int f = 0; f < 4; f++)
            wmma::store_matrix_sync(cs + (wr * 32 + m * 16) * 128 + wc * 64 + f * 16,
                                    cfrag[m][f], 128, wmma::mem_row_major);
    __syncthreads();

    // ---- epilogue: warp w owns rows w*16..w*16+15; lane owns 4 cols ----
    const int h0 = o0 >> 6;
    const int lsub = lane & 15;
    const int hsel = lane >> 4;
    float aL[4], aR[4];
#pragma unroll
    for (int c = 0; c < 4; c++) {
        aL[c] = a[lsub * 4 + c];
        aR[c] = a[64 + lsub * 4 + c];
    }
    float c0 = 0.f, c1 = 0.f, c2 = 0.f, c3 = 0.f;
#pragma unroll
    for (int rr = 0; rr < 16; rr++) {
        const int r = w * 16 + rr;
        float4 v = *(const float4*)&cs[r * 128 + lane * 4];
        __half2 p0 = __floats2half2_rn(v.x, v.y);
        __half2 p1 = __floats2half2_rn(v.z, v.w);
        g_half[(size_t)(i0 + r) * 128 + (o0 >> 2) + lane] =
            make_uint2(*(const unsigned*)&p0, *(const unsigned*)&p1);
        float pl = v.x * aL[0] + v.y * aL[1] + v.z * aL[2] + v.w * aL[3];
        float pr = v.x * aR[0] + v.y * aR[1] + v.z * aR[2] + v.w * aR[3];
#pragma unroll
        for (int o = 1; o < 16; o <<= 1) {
            pl += __shfl_xor_sync(0xFFFFFFFFu, pl, o);
            pr += __shfl_xor_sync(0xFFFFFFFFu, pr, o);
        }
        if (lsub == 0) {
            g_el[(i0 + r) * NH + h0 + hsel] = pl;
            g_er[(i0 + r) * NH + h0 + hsel] = pr;
        }
        c0 += v.x; c1 += v.y; c2 += v.z; c3 += v.w;
    }
    atomicAdd(&colsum[lane * 4 + 0], c0);
    atomicAdd(&colsum[lane * 4 + 1], c1);
    atomicAdd(&colsum[lane * 4 + 2], c2);
    atomicAdd(&colsum[lane * 4 + 3], c3);
    __syncthreads();
    if (t < 128) g_gsum_part[blockIdx.y * OF + o0 + t] = colsum[t];
}

// ---------------------------------------------------------------------------
// Fold the 32 gsum partials -> g_gsum[512]
// ---------------------------------------------------------------------------
__global__ __launch_bounds__(128) void gsum_reduce_kernel() {
    const int c = blockIdx.x * 128 + threadIdx.x;
    float s = 0.f;
#pragma unroll 16
    for (int p = 0; p < 32; p++) s += g_gsum_part[p * OF + c];
    g_gsum[c] = s;
}

// ---------------------------------------------------------------------------
// Attention: one CTA per row i, 512 threads. Phase A now reads g_bitmask.
// out[i,c] = (G_sum[c] + sum_edges w[e,h]*g[j_e,c]) / (N + sum_edges w[e,h]),
// w = exp(leaky_relu(el_i + er_j)) - 1.  Gather via __ldg (R14: __ldcg hurt).
// ---------------------------------------------------------------------------
__global__ __launch_bounds__(512) void attn_kernel(float* __restrict__ out) {
    __shared__ int   jlist[MAX_DEG];
    __shared__ __align__(16) float wsm[MAX_DEG * NH];
    __shared__ float el_sh[NH];
    __shared__ float s_sh[NH];
    __shared__ int   wsum[4];
    __shared__ int   deg_sh;
    __shared__ __align__(16) float red[7 * 512];

    const int i = blockIdx.x;
    const int t = threadIdx.x;
    const int lane = t & 31, warp = t >> 5;

    if (t < NH) { s_sh[t] = 0.f; el_sh[t] = g_el[i * NH + t]; }

    // Phase A: read precomputed bitmask, popc + prefix scan + bit extraction.
    unsigned mym = (t < 128) ? __ldg(&g_bitmask[(size_t)i * 128 + t]) : 0u;
    int myc = __popc(mym);
    int sc = myc;
#pragma unroll
    for (int o = 1; o < 32; o <<= 1) {
        int v = __shfl_up_sync(0xFFFFFFFFu, sc, o);
        if (lane >= o) sc += v;
    }
    if (t < 128 && lane == 31) wsum[warp] = sc;
    __syncthreads();
    if (t < 128) {
        int off = sc - myc;
#pragma unroll
        for (int w2 = 0; w2 < 4; w2++) if (w2 < warp) off += wsum[w2];
        int base = t * 32;
        unsigned mm = mym;
        while (mm) {
            int b = __ffs(mm) - 1;
            if (off < MAX_DEG) jlist[off] = base + b;
            off++;
            mm &= mm - 1;
        }
    }
    if (t == 0) {
        int d = wsum[0] + wsum[1] + wsum[2] + wsum[3];
        deg_sh = (d < MAX_DEG) ? d : MAX_DEG;
    }
    __syncthreads();
    const int deg = deg_sh;

    // Phase B: per-edge per-head weight w = exp(lrelu(el+er)) - 1
    float sloc[NH];
#pragma unroll
    for (int hh = 0; hh < NH; hh++) sloc[hh] = 0.f;
    if (t < deg) {
        int j = jlist[t];
        float4 er0 = *(const float4*)&g_er[j * NH + 0];
        float4 er1 = *(const float4*)&g_er[j * NH + 4];
        float erv[8] = {er0.x, er0.y, er0.z, er0.w, er1.x, er1.y, er1.z, er1.w};
#pragma unroll
        for (int hh = 0; hh < NH; hh++) {
            float x = el_sh[hh] + erv[hh];
            x = (x > 0.f) ? x : NEG_SLOPE * x;
            float w = __expf(x) - 1.f;
            wsm[t * NH + hh] = w;
            sloc[hh] = w;
        }
    }
#pragma unroll
    for (int hh = 0; hh < NH; hh++) {
#pragma unroll
        for (int o = 16; o > 0; o >>= 1)
            sloc[hh] += __shfl_xor_sync(0xFFFFFFFFu, sloc[hh], o);
    }
    if (lane == 0) {
#pragma unroll
        for (int hh = 0; hh < NH; hh++) atomicAdd(&s_sh[hh], sloc[hh]);
    }
    __syncthreads();

    // Phase C: fp16 gather, 8 substreams, software-pipelined j/w.
    const int wrd = t & 63;
    const int sub = t >> 6;
    const int hh = wrd >> 3;
    const uint4* gw = (const uint4*)g_half;
    float a0 = 0.f, a1 = 0.f, a2 = 0.f, a3 = 0.f;
    float a4 = 0.f, a5 = 0.f, a6 = 0.f, a7 = 0.f;
    int e = sub;
    int jn = 0; float wn = 0.f;
    if (e < deg) { jn = jlist[e]; wn = wsm[e * NH + hh]; }
#pragma unroll 4
    while (e < deg) {
        const int j = jn;
        const float wt = wn;
        const int en = e + 8;
        if (en < deg) { jn = jlist[en]; wn = wsm[en * NH + hh]; }
        uint4 gv = __ldg(&gw[(size_t)j * 64 + wrd]);
        float2 f0 = __half22float2(*(__half2*)&gv.x);
        float2 f1 = __half22float2(*(__half2*)&gv.y);
        float2 f2 = __half22float2(*(__half2*)&gv.z);
        float2 f3 = __half22float2(*(__half2*)&gv.w);
        a0 = fmaf(wt, f0.x, a0); a1 = fmaf(wt, f0.y, a1);
        a2 = fmaf(wt, f1.x, a2); a3 = fmaf(wt, f1.y, a3);
        a4 = fmaf(wt, f2.x, a4); a5 = fmaf(wt, f2.y, a5);
        a6 = fmaf(wt, f3.x, a6); a7 = fmaf(wt, f3.y, a7);
        e = en;
    }
    if (sub != 0) {
        float* rp = &red[(sub - 1) * 512 + wrd * 8];
        *(float4*)&rp[0] = make_float4(a0, a1, a2, a3);
        *(float4*)&rp[4] = make_float4(a4, a5, a6, a7);
    }
    __syncthreads();
    if (sub == 0) {
        float inv = 1.f / ((float)NN + s_sh[hh]);
#pragma unroll
        for (int p = 0; p < 7; p++) {
            const float* rp = &red[p * 512 + wrd * 8];
            float4 v0 = *(const float4*)&rp[0];
            float4 v1 = *(const float4*)&rp[4];
            a0 += v0.x; a1 += v0.y; a2 += v0.z; a3 += v0.w;
            a4 += v1.x; a5 += v1.y; a6 += v1.z; a7 += v1.w;
        }
        const float* gs = &g_gsum[wrd * 8];
        float4 g0 = *(const float4*)&gs[0];
        float4 g1 = *(const float4*)&gs[4];
        float4 o0, o1;
        o0.x = (a0 + g0.x) * inv; o0.y = (a1 + g0.y) * inv;
        o0.z = (a2 + g0.z) * inv; o0.w = (a3 + g0.w) * inv;
        o1.x = (a4 + g1.x) * inv; o1.y = (a5 + g1.y) * inv;
        o1.z = (a6 + g1.z) * inv; o1.w = (a7 + g1.w) * inv;
        float* op = &out[(size_t)i * OF + wrd * 8];
        *(float4*)&op[0] = o0;
        *(float4*)&op[4] = o1;
    }
}

// ---------------------------------------------------------------------------
extern "C" void kernel_launch(void* const* d_in, const int* in_sizes, int n_in,
                              void* d_out, int out_size) {
    const float* h   = (const float*)d_in[0];   // [4096, 256]
    const float* adj = (const float*)d_in[1];   // [4096, 4096, 1]
    const float* W   = (const float*)d_in[2];   // [512, 256]
    const float* a   = (const float*)d_in[3];   // [128]
    float* out = (float*)d_out;                 // [4096, 512]

    static cudaStream_t s2 = nullptr;
    static cudaEvent_t evF = nullptr, evJ = nullptr;
    if (!s2) {   // one-time host-side setup on the (uncaptured) correctness call
        cudaStreamCreateWithFlags(&s2, cudaStreamNonBlocking);
        cudaEventCreateWithFlags(&evF, cudaEventDisableTiming);
        cudaEventCreateWithFlags(&evJ, cudaEventDisableTiming);
        cudaFuncSetAttribute(gemm_wmma_kernel,
                             cudaFuncAttributeMaxDynamicSharedMemorySize, GM_SMEM);
    }

    // Fork: bitmask scan (DRAM-bound) overlapped with GEMM (tensor-bound).
    cudaEventRecord(evF, 0);
    cudaStreamWaitEvent(s2, evF, 0);
    bitmask_kernel<<<NN / 8, 256, 0, s2>>>(adj);
    gemm_wmma_kernel<<<dim3(OF / 128, NN / 128), 256, GM_SMEM>>>(h, W, a);
    gsum_reduce_kernel<<<OF / 128, 128>>>();
    // Join: attn needs both branches.
    cudaEventRecord(evJ, s2);
    cudaStreamWaitEvent(0, evJ, 0);
    attn_kernel<<<NN, 512>>>(out);
}

// round 16
// speedup vs baseline: 1.0689x; 1.0689x over previous
#include <cuda_runtime.h>
#include <cuda_fp16.h>
#include <mma.h>
#include <cstdint>

using namespace nvcuda;

#define NN 4096         // N_NODES
#define IF 256          // IN_FEAT
#define NH 8            // N_HEADS
#define HID 64          // N_HIDDEN
#define OF 512          // NH*HID
#define NEG_SLOPE 0.2f
#define MAX_DEG 512     // binomial(4096,0.05): mean 205, max ~265

// Scratch (device globals: no allocation allowed).
__device__ __align__(16) uint2 g_half[NN * 128];    // g in fp16, [4096][512] (4 MB)
__device__ __align__(16) float g_el[NN * NH];
__device__ __align__(16) float g_er[NN * NH];
__device__ __align__(16) float g_gsum_part[32 * OF];
__device__ __align__(16) float g_gsum[OF];

// ---------------------------------------------------------------------------
// WMMA GEMM: g[i,o] = sum_k h[i,k]*W[o,k].  M=4096, N=512, K=256.
// 128x128 tile, 256 thr (8 warps), grid 4x32 = 128 CTAs = ONE wave.
// In-kernel fp32->fp16 conversion while staging (whole K in smem, one sync).
// Warp (wr,wc): 32x64 warp tile -> cfrag[2][4].
// C -> smem (aliased over staging) -> warp-local epilogue.   (R14-measured 13.1us)
// ---------------------------------------------------------------------------
#define HS_STRIDE 264                              // halves/row (256+8 pad), 16B-mult
#define WS_OFF (128 * HS_STRIDE)                   // in halves
#define GM_SMEM ((128 + 128) * HS_STRIDE * 2)      // 135168 B

__global__ __launch_bounds__(256) void gemm_wmma_kernel(const float* __restrict__ h,
                                                        const float* __restrict__ W,
                                                        const float* __restrict__ a) {
    extern __shared__ __align__(16) char dynsm[];
    __half* hs = (__half*)dynsm;                   // [128][264]
    __half* ws = (__half*)dynsm + WS_OFF;          // [128][264]
    float*  cs = (float*)dynsm;                    // [128][128], aliases hs after mainloop
    __shared__ float colsum[128];

    const int t = threadIdx.x, lane = t & 31, w = t >> 5;
    const int o0 = blockIdx.x * 128, i0 = blockIdx.y * 128;

    if (t < 128) colsum[t] = 0.f;

#pragma unroll
    for (int l = t; l < 128 * 64; l += 256) {
        int row = l >> 6, c4 = l & 63;
        float4 v = *(const float4*)&h[(size_t)(i0 + row) * IF + c4 * 4];
        __half2 p0 = __floats2half2_rn(v.x, v.y);
        __half2 p1 = __floats2half2_rn(v.z, v.w);
        *(uint2*)&hs[row * HS_STRIDE + c4 * 4] =
            make_uint2(*(const unsigned*)&p0, *(const unsigned*)&p1);
    }
#pragma unroll
    for (int l = t; l < 128 * 64; l += 256) {
        int row = l >> 6, c4 = l & 63;
        float4 v = *(const float4*)&W[(size_t)(o0 + row) * IF + c4 * 4];
        __half2 p0 = __floats2half2_rn(v.x, v.y);
        __half2 p1 = __floats2half2_rn(v.z, v.w);
        *(uint2*)&ws[row * HS_STRIDE + c4 * 4] =
            make_uint2(*(const unsigned*)&p0, *(const unsigned*)&p1);
    }
    __syncthreads();

    const int wr = w >> 1, wc = w & 1;
    wmma::fragment<wmma::accumulator, 16, 16, 16, float> cfrag[2][4];
#pragma unroll
    for (int m = 0; m < 2; m++)
#pragma unroll
        for (int f = 0; f < 4; f++) wmma::fill_fragment(cfrag[m][f], 0.f);

#pragma unroll
    for (int kf = 0; kf < 16; kf++) {
        wmma::fragment<wmma::matrix_a, 16, 16, 16, __half, wmma::row_major> afrag[2];
#pragma unroll
        for (int m = 0; m < 2; m++)
            wmma::load_matrix_sync(afrag[m],
                hs + (wr * 32 + m * 16) * HS_STRIDE + kf * 16, HS_STRIDE);
#pragma unroll
        for (int f = 0; f < 4; f++) {
            wmma::fragment<wmma::matrix_b, 16, 16, 16, __half, wmma::col_major> bfrag;
            wmma::load_matrix_sync(bfrag,
                ws + (wc * 64 + f * 16) * HS_STRIDE + kf * 16, HS_STRIDE);
#pragma unroll
            for (int m = 0; m < 2; m++)
                wmma::mma_sync(cfrag[m][f], afrag[m], bfrag, cfrag[m][f]);
        }
    }
    __syncthreads();   // all reads of hs/ws done before cs (aliased) is written
#pragma unroll
    for (int m = 0; m < 2; m++)
#pragma unroll
        for (int f = 0; f < 4; f++)
            wmma::store_matrix_sync(cs + (wr * 32 + m * 16) * 128 + wc * 64 + f * 16,
                                    cfrag[m][f], 128, wmma::mem_row_major);
    __syncthreads();

    // ---- epilogue: warp w owns rows w*16..w*16+15; lane owns 4 cols ----
    const int h0 = o0 >> 6;
    const int lsub = lane & 15;
    const int hsel = lane >> 4;
    float aL[4], aR[4];
#pragma unroll
    for (int c = 0; c < 4; c++) {
        aL[c] = a[lsub * 4 + c];
        aR[c] = a[64 + lsub * 4 + c];
    }
    float c0 = 0.f, c1 = 0.f, c2 = 0.f, c3 = 0.f;
#pragma unroll
    for (int rr = 0; rr < 16; rr++) {
        const int r = w * 16 + rr;
        float4 v = *(const float4*)&cs[r * 128 + lane * 4];
        __half2 p0 = __floats2half2_rn(v.x, v.y);
        __half2 p1 = __floats2half2_rn(v.z, v.w);
        g_half[(size_t)(i0 + r) * 128 + (o0 >> 2) + lane] =
            make_uint2(*(const unsigned*)&p0, *(const unsigned*)&p1);
        float pl = v.x * aL[0] + v.y * aL[1] + v.z * aL[2] + v.w * aL[3];
        float pr = v.x * aR[0] + v.y * aR[1] + v.z * aR[2] + v.w * aR[3];
#pragma unroll
        for (int o = 1; o < 16; o <<= 1) {
            pl += __shfl_xor_sync(0xFFFFFFFFu, pl, o);
            pr += __shfl_xor_sync(0xFFFFFFFFu, pr, o);
        }
        if (lsub == 0) {
            g_el[(i0 + r) * NH + h0 + hsel] = pl;
            g_er[(i0 + r) * NH + h0 + hsel] = pr;
        }
        c0 += v.x; c1 += v.y; c2 += v.z; c3 += v.w;
    }
    atomicAdd(&colsum[lane * 4 + 0], c0);
    atomicAdd(&colsum[lane * 4 + 1], c1);
    atomicAdd(&colsum[lane * 4 + 2], c2);
    atomicAdd(&colsum[lane * 4 + 3], c3);
    __syncthreads();
    if (t < 128) g_gsum_part[blockIdx.y * OF + o0 + t] = colsum[t];
}

// ---------------------------------------------------------------------------
// Fold the 32 gsum partials -> g_gsum[512]
// ---------------------------------------------------------------------------
__global__ __launch_bounds__(128) void gsum_reduce_kernel() {
    const int c = blockIdx.x * 128 + threadIdx.x;
    float s = 0.f;
#pragma unroll 16
    for (int p = 0; p < 32; p++) s += g_gsum_part[p * OF + c];
    g_gsum[c] = s;
}

// ---------------------------------------------------------------------------
// Attention: one CTA per row i, 512 threads.  Inline ballot scan (R15 showed
// it is free inside this kernel).  Phase B builds an interleaved (w, j) table
// so phase C needs ONE LDS.64 per iteration instead of two LDS.32.
// out[i,c] = (G_sum[c] + sum_edges w[e,h]*g[j_e,c]) / (N + sum_edges w[e,h]),
// w = exp(leaky_relu(el_i + er_j)) - 1.
// ---------------------------------------------------------------------------
__global__ __launch_bounds__(512) void attn_kernel(const float* __restrict__ adj,
                                                   float* __restrict__ out) {
    __shared__ unsigned bm[128];
    __shared__ int   jlist[MAX_DEG];
    __shared__ __align__(16) uint2 wj[MAX_DEG * NH];      // (w bits, j) per edge/head, 32 KB
    __shared__ float el_sh[NH];
    __shared__ float s_sh[NH];
    __shared__ int   wsum[4];
    __shared__ int   deg_sh;
    __shared__ __align__(16) float red[7 * 512];

    const int i = blockIdx.x;
    const int t = threadIdx.x;
    const int lane = t & 31, warp = t >> 5;

    if (t < NH) { s_sh[t] = 0.f; el_sh[t] = g_el[i * NH + t]; }

    // Phase A1: ballot scan. warp w covers words w*8..w*8+7 (word = 32 cols).
    const float* arow = adj + (size_t)i * NN;
#pragma unroll
    for (int k = 0; k < 8; k++) {
        int q = warp * 8 + k;
        float v = __ldg(&arow[q * 32 + lane]);
        unsigned msk = __ballot_sync(0xFFFFFFFFu, v != 0.f);
        if (lane == 0) bm[q] = msk;
    }
    __syncthreads();

    // Phase A2: popc + 4-warp prefix scan + bit extraction into jlist.
    unsigned mym = (t < 128) ? bm[t] : 0u;
    int myc = __popc(mym);
    int sc = myc;
#pragma unroll
    for (int o = 1; o < 32; o <<= 1) {
        int v = __shfl_up_sync(0xFFFFFFFFu, sc, o);
        if (lane >= o) sc += v;
    }
    if (t < 128 && lane == 31) wsum[warp] = sc;
    __syncthreads();
    if (t < 128) {
        int off = sc - myc;
#pragma unroll
        for (int w2 = 0; w2 < 4; w2++) if (w2 < warp) off += wsum[w2];
        int base = t * 32;
        unsigned mm = mym;
        while (mm) {
            int b = __ffs(mm) - 1;
            if (off < MAX_DEG) jlist[off] = base + b;
            off++;
            mm &= mm - 1;
        }
    }
    if (t == 0) {
        int d = wsum[0] + wsum[1] + wsum[2] + wsum[3];
        deg_sh = (d < MAX_DEG) ? d : MAX_DEG;
    }
    __syncthreads();
    const int deg = deg_sh;

    // Phase B: per-edge per-head weight w = exp(lrelu(el+er)) - 1; build wj table.
    float sloc[NH];
#pragma unroll
    for (int hh = 0; hh < NH; hh++) sloc[hh] = 0.f;
    if (t < deg) {
        int j = jlist[t];
        float4 er0 = *(const float4*)&g_er[j * NH + 0];
        float4 er1 = *(const float4*)&g_er[j * NH + 4];
        float erv[8] = {er0.x, er0.y, er0.z, er0.w, er1.x, er1.y, er1.z, er1.w};
#pragma unroll
        for (int hh = 0; hh < NH; hh++) {
            float x = el_sh[hh] + erv[hh];
            x = (x > 0.f) ? x : NEG_SLOPE * x;
            float w = __expf(x) - 1.f;
            wj[t * NH + hh] = make_uint2(__float_as_uint(w), (unsigned)j);
            sloc[hh] = w;
        }
    }
#pragma unroll
    for (int hh = 0; hh < NH; hh++) {
#pragma unroll
        for (int o = 16; o > 0; o >>= 1)
            sloc[hh] += __shfl_xor_sync(0xFFFFFFFFu, sloc[hh], o);
    }
    if (lane == 0) {
#pragma unroll
        for (int hh = 0; hh < NH; hh++) atomicAdd(&s_sh[hh], sloc[hh]);
    }
    __syncthreads();

    // Phase C: fp16 gather. thread owns uint4 word (t&63) = 8 cols;
    // 8 edge substreams (t>>6, warp-uniform). One LDS.64 per iteration
    // fetches (w, j); software-pipelined one iteration ahead.
    const int wrd = t & 63;
    const int sub = t >> 6;
    const int hh = wrd >> 3;
    const uint4* gw = (const uint4*)g_half;
    float a0 = 0.f, a1 = 0.f, a2 = 0.f, a3 = 0.f;
    float a4 = 0.f, a5 = 0.f, a6 = 0.f, a7 = 0.f;
    int e = sub;
    uint2 wjn = make_uint2(0u, 0u);
    if (e < deg) wjn = wj[e * NH + hh];
#pragma unroll 4
    while (e < deg) {
        const float wt = __uint_as_float(wjn.x);
        const unsigned j = wjn.y;
        const int en = e + 8;
        if (en < deg) wjn = wj[en * NH + hh];
        uint4 gv = __ldg(&gw[(size_t)j * 64 + wrd]);
        float2 f0 = __half22float2(*(__half2*)&gv.x);
        float2 f1 = __half22float2(*(__half2*)&gv.y);
        float2 f2 = __half22float2(*(__half2*)&gv.z);
        float2 f3 = __half22float2(*(__half2*)&gv.w);
        a0 = fmaf(wt, f0.x, a0); a1 = fmaf(wt, f0.y, a1);
        a2 = fmaf(wt, f1.x, a2); a3 = fmaf(wt, f1.y, a3);
        a4 = fmaf(wt, f2.x, a4); a5 = fmaf(wt, f2.y, a5);
        a6 = fmaf(wt, f3.x, a6); a7 = fmaf(wt, f3.y, a7);
        e = en;
    }
    if (sub != 0) {
        float* rp = &red[(sub - 1) * 512 + wrd * 8];
        *(float4*)&rp[0] = make_float4(a0, a1, a2, a3);
        *(float4*)&rp[4] = make_float4(a4, a5, a6, a7);
    }
    __syncthreads();
    if (sub == 0) {
        float inv = 1.f / ((float)NN + s_sh[hh]);
#pragma unroll
        for (int p = 0; p < 7; p++) {
            const float* rp = &red[p * 512 + wrd * 8];
            float4 v0 = *(const float4*)&rp[0];
            float4 v1 = *(const float4*)&rp[4];
            a0 += v0.x; a1 += v0.y; a2 += v0.z; a3 += v0.w;
            a4 += v1.x; a5 += v1.y; a6 += v1.z; a7 += v1.w;
        }
        const float* gs = &g_gsum[wrd * 8];
        float4 g0 = *(const float4*)&gs[0];
        float4 g1 = *(const float4*)&gs[4];
        float4 o0, o1;
        o0.x = (a0 + g0.x) * inv; o0.y = (a1 + g0.y) * inv;
        o0.z = (a2 + g0.z) * inv; o0.w = (a3 + g0.w) * inv;
        o1.x = (a4 + g1.x) * inv; o1.y = (a5 + g1.y) * inv;
        o1.z = (a6 + g1.z) * inv; o1.w = (a7 + g1.w) * inv;
        float* op = &out[(size_t)i * OF + wrd * 8];
        *(float4*)&op[0] = o0;
        *(float4*)&op[4] = o1;
    }
}

// ---------------------------------------------------------------------------
extern "C" void kernel_launch(void* const* d_in, const int* in_sizes, int n_in,
                              void* d_out, int out_size) {
    const float* h   = (const float*)d_in[0];   // [4096, 256]
    const float* adj = (const float*)d_in[1];   // [4096, 4096, 1]
    const float* W   = (const float*)d_in[2];   // [512, 256]
    const float* a   = (const float*)d_in[3];   // [128]
    float* out = (float*)d_out;                 // [4096, 512]

    static bool attr_set = false;
    if (!attr_set) {
        cudaFuncSetAttribute(gemm_wmma_kernel,
                             cudaFuncAttributeMaxDynamicSharedMemorySize, GM_SMEM);
        attr_set = true;
    }

    gemm_wmma_kernel<<<dim3(OF / 128, NN / 128), 256, GM_SMEM>>>(h, W, a);
    gsum_reduce_kernel<<<OF / 128, 128>>>();
    attn_kernel<<<NN, 512>>>(adj, out);
}

// round 17
// speedup vs baseline: 1.1079x; 1.0365x over previous
#include <cuda_runtime.h>
#include <cuda_fp16.h>
#include <mma.h>
#include <cstdint>

using namespace nvcuda;

#define NN 4096         // N_NODES
#define IF 256          // IN_FEAT
#define NH 8            // N_HEADS
#define HID 64          // N_HIDDEN
#define OF 512          // NH*HID
#define NEG_SLOPE 0.2f
#define MAX_DEG 512     // binomial(4096,0.05): mean 205, max ~265

// Scratch (device globals: no allocation allowed).
__device__ __align__(16) uint2 g_half[NN * 128];    // g in fp16, [4096][512] (4 MB)
__device__ __align__(16) float g_el[NN * NH];
__device__ __align__(16) float g_er[NN * NH];
__device__ __align__(16) float g_gsum_part[32 * OF];
__device__ __align__(16) float g_gsum[OF];

// ---------------------------------------------------------------------------
// WMMA GEMM: g[i,o] = sum_k h[i,k]*W[o,k].  M=4096, N=512, K=256.
// 128x128 tile, 256 thr (8 warps), grid 4x32 = 128 CTAs = ONE wave.
// In-kernel fp32->fp16 conversion while staging (whole K in smem, one sync).
// Warp (wr,wc): 32x64 warp tile -> cfrag[2][4].
// C -> smem (aliased over staging) -> warp-local epilogue. (R14-measured 13.1us)
// ---------------------------------------------------------------------------
#define HS_STRIDE 264                              // halves/row (256+8 pad), 16B-mult
#define WS_OFF (128 * HS_STRIDE)                   // in halves
#define GM_SMEM ((128 + 128) * HS_STRIDE * 2)      // 135168 B

__global__ __launch_bounds__(256) void gemm_wmma_kernel(const float* __restrict__ h,
                                                        const float* __restrict__ W,
                                                        const float* __restrict__ a) {
    extern __shared__ __align__(16) char dynsm[];
    __half* hs = (__half*)dynsm;                   // [128][264]
    __half* ws = (__half*)dynsm + WS_OFF;          // [128][264]
    float*  cs = (float*)dynsm;                    // [128][128], aliases hs after mainloop
    __shared__ float colsum[128];

    const int t = threadIdx.x, lane = t & 31, w = t >> 5;
    const int o0 = blockIdx.x * 128, i0 = blockIdx.y * 128;

    if (t < 128) colsum[t] = 0.f;

#pragma unroll
    for (int l = t; l < 128 * 64; l += 256) {
        int row = l >> 6, c4 = l & 63;
        float4 v = *(const float4*)&h[(size_t)(i0 + row) * IF + c4 * 4];
        __half2 p0 = __floats2half2_rn(v.x, v.y);
        __half2 p1 = __floats2half2_rn(v.z, v.w);
        *(uint2*)&hs[row * HS_STRIDE + c4 * 4] =
            make_uint2(*(const unsigned*)&p0, *(const unsigned*)&p1);
    }
#pragma unroll
    for (int l = t; l < 128 * 64; l += 256) {
        int row = l >> 6, c4 = l & 63;
        float4 v = *(const float4*)&W[(size_t)(o0 + row) * IF + c4 * 4];
        __half2 p0 = __floats2half2_rn(v.x, v.y);
        __half2 p1 = __floats2half2_rn(v.z, v.w);
        *(uint2*)&ws[row * HS_STRIDE + c4 * 4] =
            make_uint2(*(const unsigned*)&p0, *(const unsigned*)&p1);
    }
    __syncthreads();

    const int wr = w >> 1, wc = w & 1;
    wmma::fragment<wmma::accumulator, 16, 16, 16, float> cfrag[2][4];
#pragma unroll
    for (int m = 0; m < 2; m++)
#pragma unroll
        for (int f = 0; f < 4; f++) wmma::fill_fragment(cfrag[m][f], 0.f);

#pragma unroll
    for (int kf = 0; kf < 16; kf++) {
        wmma::fragment<wmma::matrix_a, 16, 16, 16, __half, wmma::row_major> afrag[2];
#pragma unroll
        for (int m = 0; m < 2; m++)
            wmma::load_matrix_sync(afrag[m],
                hs + (wr * 32 + m * 16) * HS_STRIDE + kf * 16, HS_STRIDE);
#pragma unroll
        for (int f = 0; f < 4; f++) {
            wmma::fragment<wmma::matrix_b, 16, 16, 16, __half, wmma::col_major> bfrag;
            wmma::load_matrix_sync(bfrag,
                ws + (wc * 64 + f * 16) * HS_STRIDE + kf * 16, HS_STRIDE);
#pragma unroll
            for (int m = 0; m < 2; m++)
                wmma::mma_sync(cfrag[m][f], afrag[m], bfrag, cfrag[m][f]);
        }
    }
    __syncthreads();   // all reads of hs/ws done before cs (aliased) is written
#pragma unroll
    for (int m = 0; m < 2; m++)
#pragma unroll
        for (int f = 0; f < 4; f++)
            wmma::store_matrix_sync(cs + (wr * 32 + m * 16) * 128 + wc * 64 + f * 16,
                                    cfrag[m][f], 128, wmma::mem_row_major);
    __syncthreads();

    // ---- epilogue: warp w owns rows w*16..w*16+15; lane owns 4 cols ----
    const int h0 = o0 >> 6;
    const int lsub = lane & 15;
    const int hsel = lane >> 4;
    float aL[4], aR[4];
#pragma unroll
    for (int c = 0; c < 4; c++) {
        aL[c] = a[lsub * 4 + c];
        aR[c] = a[64 + lsub * 4 + c];
    }
    float c0 = 0.f, c1 = 0.f, c2 = 0.f, c3 = 0.f;
#pragma unroll
    for (int rr = 0; rr < 16; rr++) {
        const int r = w * 16 + rr;
        float4 v = *(const float4*)&cs[r * 128 + lane * 4];
        __half2 p0 = __floats2half2_rn(v.x, v.y);
        __half2 p1 = __floats2half2_rn(v.z, v.w);
        g_half[(size_t)(i0 + r) * 128 + (o0 >> 2) + lane] =
            make_uint2(*(const unsigned*)&p0, *(const unsigned*)&p1);
        float pl = v.x * aL[0] + v.y * aL[1] + v.z * aL[2] + v.w * aL[3];
        float pr = v.x * aR[0] + v.y * aR[1] + v.z * aR[2] + v.w * aR[3];
#pragma unroll
        for (int o = 1; o < 16; o <<= 1) {
            pl += __shfl_xor_sync(0xFFFFFFFFu, pl, o);
            pr += __shfl_xor_sync(0xFFFFFFFFu, pr, o);
        }
        if (lsub == 0) {
            g_el[(i0 + r) * NH + h0 + hsel] = pl;
            g_er[(i0 + r) * NH + h0 + hsel] = pr;
        }
        c0 += v.x; c1 += v.y; c2 += v.z; c3 += v.w;
    }
    atomicAdd(&colsum[lane * 4 + 0], c0);
    atomicAdd(&colsum[lane * 4 + 1], c1);
    atomicAdd(&colsum[lane * 4 + 2], c2);
    atomicAdd(&colsum[lane * 4 + 3], c3);
    __syncthreads();
    if (t < 128) g_gsum_part[blockIdx.y * OF + o0 + t] = colsum[t];
}

// ---------------------------------------------------------------------------
// Fold the 32 gsum partials -> g_gsum[512]
// ---------------------------------------------------------------------------
__global__ __launch_bounds__(128) void gsum_reduce_kernel() {
    const int c = blockIdx.x * 128 + threadIdx.x;
    float s = 0.f;
#pragma unroll 16
    for (int p = 0; p < 32; p++) s += g_gsum_part[p * OF + c];
    g_gsum[c] = s;
}

// ---------------------------------------------------------------------------
// Attention: one CTA per row i, 512 threads.
// out[i,c] = (G_sum[c] + sum_edges w[e,h]*g[j_e,c]) / (N + sum_edges w[e,h]),
// w = exp(leaky_relu(el_i + er_j)) - 1.
// Phase C: HFMA2 accumulation — weight table stored as half2(w,w) (8 KB),
// 4 HFMA2 per LDG.128, no CVTs in the loop; fp32 conversion once at the end.
// ---------------------------------------------------------------------------
__global__ __launch_bounds__(512) void attn_kernel(const float* __restrict__ adj,
                                                   float* __restrict__ out) {
    __shared__ unsigned bm[128];
    __shared__ int   jlist[MAX_DEG];
    __shared__ __align__(8) __half2 wsm2[MAX_DEG * NH];   // (w,w) fp16 pairs, 8 KB
    __shared__ float el_sh[NH];
    __shared__ float s_sh[NH];
    __shared__ int   wsum[4];
    __shared__ int   deg_sh;
    __shared__ __align__(16) float red[7 * 512];

    const int i = blockIdx.x;
    const int t = threadIdx.x;
    const int lane = t & 31, warp = t >> 5;

    if (t < NH) { s_sh[t] = 0.f; el_sh[t] = g_el[i * NH + t]; }

    // Phase A1: ballot scan. warp w covers words w*8..w*8+7 (word = 32 cols).
    const float* arow = adj + (size_t)i * NN;
#pragma unroll
    for (int k = 0; k < 8; k++) {
        int q = warp * 8 + k;
        float v = __ldg(&arow[q * 32 + lane]);
        unsigned msk = __ballot_sync(0xFFFFFFFFu, v != 0.f);
        if (lane == 0) bm[q] = msk;
    }
    __syncthreads();

    // Phase A2: popc + 4-warp prefix scan + bit extraction into jlist.
    unsigned mym = (t < 128) ? bm[t] : 0u;
    int myc = __popc(mym);
    int sc = myc;
#pragma unroll
    for (int o = 1; o < 32; o <<= 1) {
        int v = __shfl_up_sync(0xFFFFFFFFu, sc, o);
        if (lane >= o) sc += v;
    }
    if (t < 128 && lane == 31) wsum[warp] = sc;
    __syncthreads();
    if (t < 128) {
        int off = sc - myc;
#pragma unroll
        for (int w2 = 0; w2 < 4; w2++) if (w2 < warp) off += wsum[w2];
        int base = t * 32;
        unsigned mm = mym;
        while (mm) {
            int b = __ffs(mm) - 1;
            if (off < MAX_DEG) jlist[off] = base + b;
            off++;
            mm &= mm - 1;
        }
    }
    if (t == 0) {
        int d = wsum[0] + wsum[1] + wsum[2] + wsum[3];
        deg_sh = (d < MAX_DEG) ? d : MAX_DEG;
    }
    __syncthreads();
    const int deg = deg_sh;

    // Phase B: per-edge per-head weight w = exp(lrelu(el+er)) - 1 (fp32 for the
    // softmax denominator; stored as half2(w,w) for the HFMA2 gather).
    float sloc[NH];
#pragma unroll
    for (int hh = 0; hh < NH; hh++) sloc[hh] = 0.f;
    if (t < deg) {
        int j = jlist[t];
        float4 er0 = *(const float4*)&g_er[j * NH + 0];
        float4 er1 = *(const float4*)&g_er[j * NH + 4];
        float erv[8] = {er0.x, er0.y, er0.z, er0.w, er1.x, er1.y, er1.z, er1.w};
#pragma unroll
        for (int hh = 0; hh < NH; hh++) {
            float x = el_sh[hh] + erv[hh];
            x = (x > 0.f) ? x : NEG_SLOPE * x;
            float w = __expf(x) - 1.f;
            wsm2[t * NH + hh] = __float2half2_rn(w);
            sloc[hh] = w;
        }
    }
#pragma unroll
    for (int hh = 0; hh < NH; hh++) {
#pragma unroll
        for (int o = 16; o > 0; o >>= 1)
            sloc[hh] += __shfl_xor_sync(0xFFFFFFFFu, sloc[hh], o);
    }
    if (lane == 0) {
#pragma unroll
        for (int hh = 0; hh < NH; hh++) atomicAdd(&s_sh[hh], sloc[hh]);
    }
    __syncthreads();

    // Phase C: fp16 gather + HFMA2 accumulate. thread owns uint4 word (t&63);
    // 8 edge substreams (t>>6, warp-uniform). Software-pipelined j/wt2.
    const int wrd = t & 63;
    const int sub = t >> 6;
    const int hh = wrd >> 3;
    const uint4* gw = (const uint4*)g_half;
    __half2 acc0 = __float2half2_rn(0.f), acc1 = acc0, acc2 = acc0, acc3 = acc0;
    int e = sub;
    int jn = 0;
    __half2 wn = __float2half2_rn(0.f);
    if (e < deg) { jn = jlist[e]; wn = wsm2[e * NH + hh]; }
#pragma unroll 4
    while (e < deg) {
        const int j = jn;
        const __half2 wt2 = wn;
        const int en = e + 8;
        if (en < deg) { jn = jlist[en]; wn = wsm2[en * NH + hh]; }
        uint4 gv = __ldg(&gw[(size_t)j * 64 + wrd]);
        acc0 = __hfma2(wt2, *(__half2*)&gv.x, acc0);
        acc1 = __hfma2(wt2, *(__half2*)&gv.y, acc1);
        acc2 = __hfma2(wt2, *(__half2*)&gv.z, acc2);
        acc3 = __hfma2(wt2, *(__half2*)&gv.w, acc3);
        e = en;
    }
    float2 f0 = __half22float2(acc0);
    float2 f1 = __half22float2(acc1);
    float2 f2 = __half22float2(acc2);
    float2 f3 = __half22float2(acc3);
    if (sub != 0) {
        float* rp = &red[(sub - 1) * 512 + wrd * 8];
        *(float4*)&rp[0] = make_float4(f0.x, f0.y, f1.x, f1.y);
        *(float4*)&rp[4] = make_float4(f2.x, f2.y, f3.x, f3.y);
    }
    __syncthreads();
    if (sub == 0) {
        float a0 = f0.x, a1 = f0.y, a2 = f1.x, a3 = f1.y;
        float a4 = f2.x, a5 = f2.y, a6 = f3.x, a7 = f3.y;
        float inv = 1.f / ((float)NN + s_sh[hh]);
#pragma unroll
        for (int p = 0; p < 7; p++) {
            const float* rp = &red[p * 512 + wrd * 8];
            float4 v0 = *(const float4*)&rp[0];
            float4 v1 = *(const float4*)&rp[4];
            a0 += v0.x; a1 += v0.y; a2 += v0.z; a3 += v0.w;
            a4 += v1.x; a5 += v1.y; a6 += v1.z; a7 += v1.w;
        }
        const float* gs = &g_gsum[wrd * 8];
        float4 g0 = *(const float4*)&gs[0];
        float4 g1 = *(const float4*)&gs[4];
        float4 o0, o1;
        o0.x = (a0 + g0.x) * inv; o0.y = (a1 + g0.y) * inv;
        o0.z = (a2 + g0.z) * inv; o0.w = (a3 + g0.w) * inv;
        o1.x = (a4 + g1.x) * inv; o1.y = (a5 + g1.y) * inv;
        o1.z = (a6 + g1.z) * inv; o1.w = (a7 + g1.w) * inv;
        float* op = &out[(size_t)i * OF + wrd * 8];
        *(float4*)&op[0] = o0;
        *(float4*)&op[4] = o1;
    }
}

// ---------------------------------------------------------------------------
extern "C" void kernel_launch(void* const* d_in, const int* in_sizes, int n_in,
                              void* d_out, int out_size) {
    const float* h   = (const float*)d_in[0];   // [4096, 256]
    const float* adj = (const float*)d_in[1];   // [4096, 4096, 1]
    const float* W   = (const float*)d_in[2];   // [512, 256]
    const float* a   = (const float*)d_in[3];   // [128]
    float* out = (float*)d_out;                 // [4096, 512]

    static bool attr_set = false;
    if (!attr_set) {
        cudaFuncSetAttribute(gemm_wmma_kernel,
                             cudaFuncAttributeMaxDynamicSharedMemorySize, GM_SMEM);
        attr_set = true;
    }

    gemm_wmma_kernel<<<dim3(OF / 128, NN / 128), 256, GM_SMEM>>>(h, W, a);
    gsum_reduce_kernel<<<OF / 128, 128>>>();
    attn_kernel<<<NN, 512>>>(adj, out);
}